// round 4
// baseline (speedup 1.0000x reference)
#include <cuda_runtime.h>
#include <cuda_fp16.h>
#include <cstdint>

// NTXentLoss fused: B=8192, D=128, G=16, T=0.5
//   prep:   normalize rows, fold (1/T)*log2(e) into zis side, cast to fp16;
//           also compute EXACT fp32 positives diag_i = cos(zis_i, zjs_i)
//   main:   per-64-row CTA: stream all 8192 cols in 128-col chunks through
//           mma.sync fp16 GEMM (cp.async double-buffered B staging),
//           fused exp2 + full-block mask + row-sum epilogue
//   final:  per-row: loss = ln(S_neg + exp(2*diag)) - 2*diag; reduce.
//
// logits in log2 domain: acc = (sim/T)*log2e, so exp = exp2f(acc).

#define B_N 8192
#define D_K 128
#define NCHUNK 128
#define NCHUNKS (B_N / NCHUNK)      // 64
#define ROWTILE 64
#define NCTAS (B_N / ROWTILE)       // 128
#define LOG2E 1.4426950408889634f
#define BUF_HALFS (NCHUNK * D_K)    // 16384 halfs = 32 KB per stage
#define SMEM_BYTES (2 * BUF_HALFS * 2 + (2 * ROWTILE + ROWTILE) * 4)

__device__ __half g_a[B_N * D_K];   // zis, scaled by (1/norm)*(2*log2e)
__device__ __half g_b[B_N * D_K];   // zjs, scaled by (1/norm)
__device__ float g_diag[B_N];       // exact fp32 cosine(zis_i, zjs_i)
__device__ float g_partial[NCTAS];

__device__ __forceinline__ uint32_t smem_u32(const void* p) {
    return (uint32_t)__cvta_generic_to_shared(p);
}

// ---------------------------------------------------------------------------
// prep: one warp per row. warps [0,8192): zis; [8192,16384): zjs;
//       [16384,24576): exact fp32 diagonal cosine.
// ---------------------------------------------------------------------------
__global__ void __launch_bounds__(256) prep_kernel(const float* __restrict__ zis,
                                                   const float* __restrict__ zjs) {
    int gwarp = (blockIdx.x * 256 + threadIdx.x) >> 5;
    int lane = threadIdx.x & 31;

    if (gwarp < 2 * B_N) {
        int which = (gwarp >= B_N) ? 1 : 0;
        int row = which ? (gwarp - B_N) : gwarp;
        const float* src = which ? zjs : zis;
        float4 v = reinterpret_cast<const float4*>(src)[row * (D_K / 4) + lane];
        float s = v.x * v.x + v.y * v.y + v.z * v.z + v.w * v.w;
#pragma unroll
        for (int o = 16; o; o >>= 1) s += __shfl_xor_sync(0xffffffffu, s, o);
        float scale = rsqrtf(fmaxf(s, 1e-24f));
        if (!which) scale *= 2.0f * LOG2E;  // (1/T) * log2(e)
        __half2 p0 = __floats2half2_rn(v.x * scale, v.y * scale);
        __half2 p1 = __floats2half2_rn(v.z * scale, v.w * scale);
        uint2 u;
        u.x = *reinterpret_cast<uint32_t*>(&p0);
        u.y = *reinterpret_cast<uint32_t*>(&p1);
        __half* dst = which ? g_b : g_a;
        // uint2 = 4 halfs -> a 128-half row is D_K/4 = 32 uint2 (stride fix!)
        reinterpret_cast<uint2*>(dst)[row * (D_K / 4) + lane] = u;
    } else {
        int row = gwarp - 2 * B_N;
        float4 vi = reinterpret_cast<const float4*>(zis)[row * (D_K / 4) + lane];
        float4 vj = reinterpret_cast<const float4*>(zjs)[row * (D_K / 4) + lane];
        float d = vi.x * vj.x + vi.y * vj.y + vi.z * vj.z + vi.w * vj.w;
        float a2 = vi.x * vi.x + vi.y * vi.y + vi.z * vi.z + vi.w * vi.w;
        float b2 = vj.x * vj.x + vj.y * vj.y + vj.z * vj.z + vj.w * vj.w;
#pragma unroll
        for (int o = 16; o; o >>= 1) {
            d += __shfl_xor_sync(0xffffffffu, d, o);
            a2 += __shfl_xor_sync(0xffffffffu, a2, o);
            b2 += __shfl_xor_sync(0xffffffffu, b2, o);
        }
        if (lane == 0)
            g_diag[row] = d / fmaxf(sqrtf(a2) * sqrtf(b2), 1e-8f);
    }
}

// ---------------------------------------------------------------------------
// cp.async stage of one 128-col x 128-k fp16 chunk into swizzled smem buffer.
// Swizzle: 16B chunk index c stored at c ^ (j & 7) within row j.
// ---------------------------------------------------------------------------
__device__ __forceinline__ void stage_chunk(uint32_t sm_base, int cb, int tid) {
#pragma unroll
    for (int i = 0; i < 8; i++) {
        int u = tid + i * 256;
        int j = u >> 4, c = u & 15;
        const __half* src = &g_b[(cb + j) * D_K + c * 8];
        uint32_t dst = sm_base + (((j << 4) + (c ^ (j & 7))) << 4);
        asm volatile("cp.async.cg.shared.global [%0], [%1], 16;\n"
                     :: "r"(dst), "l"(src));
    }
    asm volatile("cp.async.commit_group;\n");
}

// ---------------------------------------------------------------------------
// main: 128 CTAs x 256 threads. CTA = 64 rows x all 8192 cols.
// Warp grid 4x2: warp-row owns 16 rows, warp-col owns 64 of 128 chunk cols.
// A fragments preloaded to registers (reused across 64 chunks).
// B double-buffered via cp.async; read via ldmatrix.x4.
// ---------------------------------------------------------------------------
__global__ void __launch_bounds__(256, 1) main_kernel() {
    extern __shared__ __align__(1024) unsigned char dynsm[];
    __half* Bs = reinterpret_cast<__half*>(dynsm);              // 2 x 32 KB
    float* rowsum_sm = reinterpret_cast<float*>(dynsm + 2 * BUF_HALFS * 2); // [2][64]
    float* loss_sm = rowsum_sm + 2 * ROWTILE;

    const int tid = threadIdx.x;
    const int lane = tid & 31;
    const int warp = tid >> 5;
    const int wr = warp >> 1;   // 0..3
    const int wc = warp & 1;    // 0..1
    const int rb = blockIdx.x * ROWTILE;
    const int g = lane >> 2;    // groupID
    const int t4 = lane & 3;    // threadID in group

    // Preload A fragments: 8 k-steps x 4 regs (f16x2) per thread.
    uint32_t aF[8][4];
    {
        const int row0 = rb + wr * 16 + g;
        const int row1 = row0 + 8;
#pragma unroll
        for (int ks = 0; ks < 8; ks++) {
            int k0 = ks * 16 + 2 * t4;
            aF[ks][0] = *reinterpret_cast<const uint32_t*>(&g_a[row0 * D_K + k0]);
            aF[ks][1] = *reinterpret_cast<const uint32_t*>(&g_a[row1 * D_K + k0]);
            aF[ks][2] = *reinterpret_cast<const uint32_t*>(&g_a[row0 * D_K + k0 + 8]);
            aF[ks][3] = *reinterpret_cast<const uint32_t*>(&g_a[row1 * D_K + k0 + 8]);
        }
    }

    float rs0 = 0.f, rs1 = 0.f;           // per-thread row expsum accumulators
    const int nb = wc * 64;               // warp's column base within chunk
    const int mask_chunk = blockIdx.x >> 1;
    const uint32_t buf0 = smem_u32(Bs);
    const uint32_t buf1 = buf0 + BUF_HALFS * 2;

    stage_chunk(buf0, 0, tid);            // prologue: chunk 0 into buffer 0

    for (int m = 0; m < NCHUNKS; m++) {
        if (m + 1 < NCHUNKS) {
            stage_chunk((m & 1) ? buf0 : buf1, (m + 1) * NCHUNK, tid);
            asm volatile("cp.async.wait_group 1;\n");
        } else {
            asm volatile("cp.async.wait_group 0;\n");
        }
        __syncthreads();   // buffer m ready for all warps
        const uint32_t bs_base = (m & 1) ? buf1 : buf0;
        const int cb = m * NCHUNK;

        float acc[8][4];
#pragma unroll
        for (int f = 0; f < 8; f++)
#pragma unroll
            for (int e = 0; e < 4; e++) acc[f][e] = 0.f;

#pragma unroll
        for (int ks = 0; ks < 8; ks++) {
            uint32_t bF[8][2];
#pragma unroll
            for (int nf = 0; nf < 4; nf++) {
                // ldmatrix.x4 covers 16 cols x 16 k for this k-step
                int j = nb + nf * 16 + ((lane >> 4) << 3) + (lane & 7);
                int kc = 2 * ks + ((lane >> 3) & 1);
                uint32_t addr = bs_base + (((j << 4) + (kc ^ (j & 7))) << 4);
                uint32_t r0, r1, r2, r3;
                asm volatile("ldmatrix.sync.aligned.m8n8.x4.shared.b16 {%0,%1,%2,%3}, [%4];"
                             : "=r"(r0), "=r"(r1), "=r"(r2), "=r"(r3)
                             : "r"(addr));
                bF[nf * 2][0] = r0;     bF[nf * 2][1] = r1;
                bF[nf * 2 + 1][0] = r2; bF[nf * 2 + 1][1] = r3;
            }
#pragma unroll
            for (int f = 0; f < 8; f++) {
                asm volatile(
                    "mma.sync.aligned.m16n8k16.row.col.f32.f16.f16.f32 "
                    "{%0,%1,%2,%3},{%4,%5,%6,%7},{%8,%9},{%0,%1,%2,%3};"
                    : "+f"(acc[f][0]), "+f"(acc[f][1]), "+f"(acc[f][2]), "+f"(acc[f][3])
                    : "r"(aF[ks][0]), "r"(aF[ks][1]), "r"(aF[ks][2]), "r"(aF[ks][3]),
                      "r"(bF[f][0]), "r"(bF[f][1]));
            }
        }

        // Fused epilogue: exp2 + (rarely) full-block mask + per-row partial sums.
        float s0 = 0.f, s1 = 0.f;
        if (m == mask_chunk) {
            const int r0g = rb + wr * 16 + g;
            const int r1g = r0g + 8;
#pragma unroll
            for (int f = 0; f < 8; f++) {
                int c0 = cb + nb + f * 8 + 2 * t4;
#pragma unroll
                for (int e = 0; e < 4; e++) {
                    int r = (e < 2) ? r0g : r1g;
                    int c = c0 + (e & 1);
                    float ev = exp2f(acc[f][e]);
                    // mask ENTIRE own block, diagonal included
                    // (positive re-added exactly in the finalize step)
                    if ((r >> 4) == (c >> 4)) ev = 0.f;
                    if (e < 2) s0 += ev; else s1 += ev;
                }
            }
        } else {
#pragma unroll
            for (int f = 0; f < 8; f++) {
                s0 += exp2f(acc[f][0]) + exp2f(acc[f][1]);
                s1 += exp2f(acc[f][2]) + exp2f(acc[f][3]);
            }
        }
        // quad reduction: lanes {4g..4g+3} hold cols of the same rows
        s0 += __shfl_xor_sync(0xffffffffu, s0, 1);
        s0 += __shfl_xor_sync(0xffffffffu, s0, 2);
        s1 += __shfl_xor_sync(0xffffffffu, s1, 1);
        s1 += __shfl_xor_sync(0xffffffffu, s1, 2);
        rs0 += s0;
        rs1 += s1;
        __syncthreads();   // all reads of this buffer done before restage
    }

    if (t4 == 0) {
        rowsum_sm[wc * ROWTILE + wr * 16 + g] = rs0;
        rowsum_sm[wc * ROWTILE + wr * 16 + g + 8] = rs1;
    }
    __syncthreads();
    if (tid < ROWTILE) {
        float S = rowsum_sm[tid] + rowsum_sm[ROWTILE + tid];   // negatives
        float d = g_diag[rb + tid];                            // exact fp32 cosine
        float pos_logit = 2.0f * d;                            // sim / T
        S += exp2f(pos_logit * LOG2E);                         // add positive
        loss_sm[tid] = logf(S) - pos_logit;
    }
    __syncthreads();
    if (tid == 0) {
        float t = 0.f;
        for (int i = 0; i < ROWTILE; i++) t += loss_sm[i];
        g_partial[blockIdx.x] = t;
    }
}

// ---------------------------------------------------------------------------
// finalize: sum 128 partials, divide by B
// ---------------------------------------------------------------------------
__global__ void finalize_kernel(float* __restrict__ out) {
    __shared__ float sm[NCTAS];
    int tid = threadIdx.x;
    sm[tid] = g_partial[tid];
    __syncthreads();
    for (int o = NCTAS / 2; o; o >>= 1) {
        if (tid < o) sm[tid] += sm[tid + o];
        __syncthreads();
    }
    if (tid == 0) out[0] = sm[0] * (1.0f / (float)B_N);
}

extern "C" void kernel_launch(void* const* d_in, const int* in_sizes, int n_in,
                              void* d_out, int out_size) {
    (void)in_sizes; (void)n_in; (void)out_size;
    const float* zis = (const float*)d_in[0];
    const float* zjs = (const float*)d_in[1];
    cudaFuncSetAttribute(main_kernel, cudaFuncAttributeMaxDynamicSharedMemorySize,
                         SMEM_BYTES);
    prep_kernel<<<(3 * B_N * 32) / 256, 256>>>(zis, zjs);   // 3072 blocks
    main_kernel<<<NCTAS, 256, SMEM_BYTES>>>();
    finalize_kernel<<<1, NCTAS>>>((float*)d_out);
}